// round 1
// baseline (speedup 1.0000x reference)
#include <cuda_runtime.h>
#include <math.h>

#define NH 4
#define HD 128
#define D  512
#define TS 24
#define NB 64
#define SS 512
#define NPOS (NB*SS)   /* 32768 */
#define J   (NH*TS)    /* 96 */

// ---------------- device scratch (no allocations allowed) ----------------
__device__ __align__(16) float g_A [NB*NH*HD];      // user part of q: [b][h][e]
__device__ __align__(16) float g_Bq[TS*NH*HD];      // time part of q + bq: [t][h][e]
__device__ __align__(16) float g_K [TS*NH*HD];      // keys:   [k][h][e]
__device__ __align__(16) float g_V [TS*NH*HD];      // values: [k][h][e]
__device__ __align__(16) float g_E [NB*TS*NH*TS];   // exp(scores): [b][t][h][k]
__device__ __align__(16) float g_VU[J*D];           // V@Wu^T folded: [j=h*24+k][d]
__device__ __align__(16) float g_TL[J*TS];          // V@Wt^T folded: [j][d]

// ---------------- helpers ----------------
template<int N>
__device__ __forceinline__ float dotT(const float* __restrict__ a,
                                      const float* __restrict__ b) {
    float s0=0.f, s1=0.f, s2=0.f, s3=0.f;
    #pragma unroll
    for (int e = 0; e < N; e += 16) {
        float4 a0 = __ldg((const float4*)(a+e));
        float4 b0 = __ldg((const float4*)(b+e));
        s0 = fmaf(a0.x,b0.x, fmaf(a0.y,b0.y, fmaf(a0.z,b0.z, fmaf(a0.w,b0.w, s0))));
        float4 a1 = __ldg((const float4*)(a+e+4));
        float4 b1 = __ldg((const float4*)(b+e+4));
        s1 = fmaf(a1.x,b1.x, fmaf(a1.y,b1.y, fmaf(a1.z,b1.z, fmaf(a1.w,b1.w, s1))));
        float4 a2 = __ldg((const float4*)(a+e+8));
        float4 b2 = __ldg((const float4*)(b+e+8));
        s2 = fmaf(a2.x,b2.x, fmaf(a2.y,b2.y, fmaf(a2.z,b2.z, fmaf(a2.w,b2.w, s2))));
        float4 a3 = __ldg((const float4*)(a+e+12));
        float4 b3 = __ldg((const float4*)(b+e+12));
        s3 = fmaf(a3.x,b3.x, fmaf(a3.y,b3.y, fmaf(a3.z,b3.z, fmaf(a3.w,b3.w, s3))));
    }
    return (s0+s1)+(s2+s3);
}

// ---------------- K1: A, Bq, K, V (all K=512 dots, 69632 outputs) ----------------
__global__ void __launch_bounds__(256)
k_pre1(const float* __restrict__ ts_emb, const int* __restrict__ user_x,
       const float* __restrict__ upt,
       const float* __restrict__ Wq, const float* __restrict__ bq,
       const float* __restrict__ Wk, const float* __restrict__ bk,
       const float* __restrict__ Wv, const float* __restrict__ bv)
{
    int idx = blockIdx.x*256 + threadIdx.x;
    if (idx < 32768) {                         // g_A[b][he]
        int b = idx >> 9, he = idx & 511;
        const float* x = upt + (size_t)__ldg(user_x+b)*D;
        g_A[idx] = dotT<512>(Wq + (size_t)he*1024, x);
    } else if (idx < 45056) {                  // g_Bq[t][he]
        int i = idx - 32768; int t = i >> 9, he = i & 511;
        g_Bq[i] = dotT<512>(Wq + (size_t)he*1024 + 512, ts_emb + t*D) + __ldg(bq+he);
    } else if (idx < 57344) {                  // g_K[t][he]
        int i = idx - 45056; int t = i >> 9, he = i & 511;
        g_K[i] = dotT<512>(Wk + (size_t)he*512, ts_emb + t*D) + __ldg(bk+he);
    } else {                                   // g_V[t][he]
        int i = idx - 57344; int t = i >> 9, he = i & 511;
        g_V[i] = dotT<512>(Wv + (size_t)he*512, ts_emb + t*D) + __ldg(bv+he);
    }
}

// ---------------- K2: fold V through W_unify / W_time ----------------
__global__ void __launch_bounds__(256)
k_pre2(const float* __restrict__ Wu, const float* __restrict__ Wt)
{
    int idx = blockIdx.x*256 + threadIdx.x;   // 51456 total
    if (idx < J*D) {
        int j = idx >> 9, d = idx & 511;
        int h = j / TS, k = j - h*TS;
        g_VU[idx] = dotT<128>(&g_V[(k*NH + h)*HD], Wu + (size_t)d*D + h*HD);
    } else {
        int i = idx - J*D;                    // < 2304
        int j = i / TS, d = i - j*TS;
        int h = j / TS, k = j - h*TS;
        g_TL[i] = dotT<128>(&g_V[(k*NH + h)*HD], Wt + (size_t)d*D + h*HD);
    }
}

// ---------------- K3: E[b][t][h][k] = exp(scale * (A+Bq).K) ----------------
__global__ void __launch_bounds__(256)
k_pre3()
{
    int idx = blockIdx.x*256 + threadIdx.x;   // 147456
    int k = idx % TS;
    int h = (idx / TS) & 3;
    int t = (idx / (TS*NH)) % TS;
    int b = idx / (TS*NH*TS);
    const float* A = &g_A [(b*NH + h)*HD];
    const float* B = &g_Bq[(t*NH + h)*HD];
    const float* K = &g_K [(k*NH + h)*HD];
    float s0=0.f, s1=0.f, s2=0.f, s3=0.f;
    #pragma unroll
    for (int e = 0; e < HD; e += 16) {
        float4 a0 = *(const float4*)(A+e),   b0 = *(const float4*)(B+e),   k0 = *(const float4*)(K+e);
        s0 = fmaf(a0.x+b0.x,k0.x, fmaf(a0.y+b0.y,k0.y, fmaf(a0.z+b0.z,k0.z, fmaf(a0.w+b0.w,k0.w, s0))));
        float4 a1 = *(const float4*)(A+e+4), b1 = *(const float4*)(B+e+4), k1 = *(const float4*)(K+e+4);
        s1 = fmaf(a1.x+b1.x,k1.x, fmaf(a1.y+b1.y,k1.y, fmaf(a1.z+b1.z,k1.z, fmaf(a1.w+b1.w,k1.w, s1))));
        float4 a2 = *(const float4*)(A+e+8), b2 = *(const float4*)(B+e+8), k2 = *(const float4*)(K+e+8);
        s2 = fmaf(a2.x+b2.x,k2.x, fmaf(a2.y+b2.y,k2.y, fmaf(a2.z+b2.z,k2.z, fmaf(a2.w+b2.w,k2.w, s2))));
        float4 a3 = *(const float4*)(A+e+12),b3 = *(const float4*)(B+e+12),k3 = *(const float4*)(K+e+12);
        s3 = fmaf(a3.x+b3.x,k3.x, fmaf(a3.y+b3.y,k3.y, fmaf(a3.z+b3.z,k3.z, fmaf(a3.w+b3.w,k3.w, s3))));
    }
    float sc = ((s0+s1)+(s2+s3)) * 0.08838834764831845f;  // 1/sqrt(128)
    g_E[idx] = expf(sc);
}

// ---------------- K4: masked softmax + attn @ [VU | TL] ----------------
__global__ void __launch_bounds__(256)
k_main(const int* __restrict__ hour_x, const int* __restrict__ hour_mask,
       const float* __restrict__ b_unify, const float* __restrict__ b_time,
       float* __restrict__ out_emb, float* __restrict__ out_tl)
{
    __shared__ float s_attn[64][J+1];   // +1 pad: kills 2-way bank conflict
    __shared__ float s_tl[J][TS];

    const int tid = threadIdx.x;
    const int n0  = blockIdx.x * 64;

    for (int i = tid; i < J*TS; i += 256)
        (&s_tl[0][0])[i] = g_TL[i];

    // ---- phase 1: per-position masked softmax (4 threads/pos, one per head)
    {
        int p = tid & 63;
        int h = tid >> 6;
        int n = n0 + p;
        int b = n >> 9;
        int t = __ldg(hour_x + n);
        const int4*   mrow = (const int4*)(hour_mask + (size_t)n*TS);
        const float4* erow = (const float4*)(&g_E[((b*TS + t)*NH + h)*TS]);
        float wv[TS];
        float sum = 0.f;
        #pragma unroll
        for (int q = 0; q < 6; q++) {
            int4   m = __ldg(mrow + q);
            float4 e = erow[q];
            wv[4*q+0] = (m.x == 1) ? 0.f : e.x;
            wv[4*q+1] = (m.y == 1) ? 0.f : e.y;
            wv[4*q+2] = (m.z == 1) ? 0.f : e.z;
            wv[4*q+3] = (m.w == 1) ? 0.f : e.w;
            sum += (wv[4*q+0]+wv[4*q+1]) + (wv[4*q+2]+wv[4*q+3]);
        }
        float inv = 1.f / sum;
        #pragma unroll
        for (int k = 0; k < TS; k++) s_attn[p][h*TS + k] = wv[k] * inv;
    }
    __syncthreads();

    // ---- phase 2: 64x512 = attn[64x96] @ VU[96x512], reg-tiled 4x8
    const int tx = tid & 15;
    const int ty = tid >> 4;
    const int p0 = ty * 4;

    for (int c = 0; c < 4; c++) {
        const int d0 = c*128 + tx*8;
        float4 acc[4][2];
        #pragma unroll
        for (int i = 0; i < 4; i++) {
            acc[i][0] = make_float4(0.f,0.f,0.f,0.f);
            acc[i][1] = make_float4(0.f,0.f,0.f,0.f);
        }
        const float* vp = g_VU + d0;
        #pragma unroll 8
        for (int k = 0; k < J; k++) {
            float4 v0 = __ldg((const float4*)(vp + k*D));
            float4 v1 = __ldg((const float4*)(vp + k*D + 4));
            #pragma unroll
            for (int i = 0; i < 4; i++) {
                float a = s_attn[p0+i][k];
                acc[i][0].x = fmaf(a, v0.x, acc[i][0].x);
                acc[i][0].y = fmaf(a, v0.y, acc[i][0].y);
                acc[i][0].z = fmaf(a, v0.z, acc[i][0].z);
                acc[i][0].w = fmaf(a, v0.w, acc[i][0].w);
                acc[i][1].x = fmaf(a, v1.x, acc[i][1].x);
                acc[i][1].y = fmaf(a, v1.y, acc[i][1].y);
                acc[i][1].z = fmaf(a, v1.z, acc[i][1].z);
                acc[i][1].w = fmaf(a, v1.w, acc[i][1].w);
            }
        }
        float4 bu0 = __ldg((const float4*)(b_unify + d0));
        float4 bu1 = __ldg((const float4*)(b_unify + d0 + 4));
        #pragma unroll
        for (int i = 0; i < 4; i++) {
            float4 r0 = acc[i][0]; r0.x+=bu0.x; r0.y+=bu0.y; r0.z+=bu0.z; r0.w+=bu0.w;
            float4 r1 = acc[i][1]; r1.x+=bu1.x; r1.y+=bu1.y; r1.z+=bu1.z; r1.w+=bu1.w;
            float* orow = out_emb + (size_t)(n0+p0+i)*D + d0;
            *(float4*)(orow)     = r0;
            *(float4*)(orow + 4) = r1;
        }
    }

    // ---- phase 3: time logits = attn @ TL[96x24]
    #pragma unroll
    for (int r = 0; r < 6; r++) {
        int o = tid + 256*r;          // 0..1535 over 64 pos x 24 dims
        int p = o / TS;
        int d = o - p*TS;
        float acc = 0.f;
        #pragma unroll 8
        for (int j = 0; j < J; j++)
            acc = fmaf(s_attn[p][j], s_tl[j][d], acc);
        out_tl[(size_t)(n0+p)*TS + d] = acc + __ldg(b_time + d);
    }
}

// ---------------- launch ----------------
extern "C" void kernel_launch(void* const* d_in, const int* in_sizes, int n_in,
                              void* d_out, int out_size)
{
    const float* ts_emb    = (const float*)d_in[0];
    // d_in[1] smoothed_timeslot_embedded: unused by reference
    // d_in[2] user_embedded: unused by reference
    const int*   user_x    = (const int*)  d_in[3];
    const int*   hour_x    = (const int*)  d_in[4];
    const int*   hour_mask = (const int*)  d_in[5];
    const float* upt       = (const float*)d_in[6];
    const float* Wq        = (const float*)d_in[7];
    const float* bq        = (const float*)d_in[8];
    const float* Wk        = (const float*)d_in[9];
    const float* bk        = (const float*)d_in[10];
    const float* Wv        = (const float*)d_in[11];
    const float* bv        = (const float*)d_in[12];
    const float* Wu        = (const float*)d_in[13];
    const float* bu        = (const float*)d_in[14];
    const float* Wt        = (const float*)d_in[15];
    const float* bt        = (const float*)d_in[16];

    float* out_emb = (float*)d_out;
    float* out_tl  = out_emb + (size_t)NPOS * D;

    k_pre1<<<272, 256>>>(ts_emb, user_x, upt, Wq, bq, Wk, bk, Wv, bv);
    k_pre2<<<201, 256>>>(Wu, Wt);
    k_pre3<<<576, 256>>>();
    k_main<<<512, 256>>>(hour_x, hour_mask, bu, bt, out_emb, out_tl);
}